// round 2
// baseline (speedup 1.0000x reference)
#include <cuda_runtime.h>
#include <cuda_bf16.h>
#include <cstdint>

// Fixed problem geometry (reference: H_IMG=352, W_IMG=640, item=0)
#define H_IMG 352
#define W_IMG 640
#define NPIX  (H_IMG * W_IMG)

// Scratch: packed (z_bits << 32 | point_idx) per pixel. Sentinel = all ones
// (set via cudaMemsetAsync 0xFF each call).
__device__ unsigned long long g_zidx[NPIX];

static constexpr unsigned long long SENTINEL = 0xFFFFFFFFFFFFFFFFULL;

// One thread processes 4 points via 3x float4 loads (N divisible by 4).
__global__ void splat4_kernel(const float4* __restrict__ m4,
                              const float* __restrict__ Kmat,
                              const float* __restrict__ E,
                              int N4) {
    __shared__ float sE[12];  // rows 0..2 of E (R | t)
    __shared__ float sK[4];   // fx, cx, fy, cy

    if (threadIdx.x < 12) sE[threadIdx.x] = E[threadIdx.x];
    if (threadIdx.x < 4) {
        const int kidx[4] = {0, 2, 4, 5};
        sK[threadIdx.x] = Kmat[kidx[threadIdx.x]];
    }
    __syncthreads();

    int i4 = blockIdx.x * blockDim.x + threadIdx.x;
    if (i4 >= N4) return;

    float4 a = m4[3 * i4 + 0];
    float4 b = m4[3 * i4 + 1];
    float4 c = m4[3 * i4 + 2];

    float xs[4] = {a.x, a.w, b.z, c.y};
    float ys[4] = {a.y, b.x, b.w, c.z};
    float zs[4] = {a.z, b.y, c.x, c.w};

    float e0 = sE[0], e1 = sE[1], e2 = sE[2],  e3 = sE[3];
    float e4 = sE[4], e5 = sE[5], e6 = sE[6],  e7 = sE[7];
    float e8 = sE[8], e9 = sE[9], e10 = sE[10], e11 = sE[11];
    float fx = sK[0], cx = sK[1], fy = sK[2], cy = sK[3];

    int base = 4 * i4;

#pragma unroll
    for (int k = 0; k < 4; k++) {
        float x = xs[k], y = ys[k], zc = zs[k];

        float px = e0 * x + e1 * y + e2  * zc + e3;
        float py = e4 * x + e5 * y + e6  * zc + e7;
        float pz = e8 * x + e9 * y + e10 * zc + e11;

        bool valid = pz > 0.1f;
        float zsafe = valid ? pz : 1.0f;

        // Exact rn division + un-fused mul/add so int truncation boundaries
        // match the reference's unfused f32 ops.
        float ru = __fdiv_rn(px, zsafe);
        float rv = __fdiv_rn(py, zsafe);
        float uf = __fadd_rn(__fmul_rn(ru, fx), cx);
        float vf = __fadd_rn(__fmul_rn(rv, fy), cy);
        int u = (int)uf;
        int v = (int)vf;

        bool inb = valid & (u >= 0) & (u < W_IMG) & (v >= 0) & (v < H_IMG);
        if (inb) {
            int pix = v * W_IMG + u;
            unsigned long long packed =
                ((unsigned long long)__float_as_uint(pz) << 32) |
                (unsigned int)(base + k);
            atomicMin(&g_zidx[pix], packed);
        }
    }
}

__device__ __forceinline__ float fast_sigmoid(float x) {
    return __frcp_rn(1.0f + __expf(-x));
}

// 2 pixels per thread: 16B zbuf read, float2 plane writes.
__global__ void render2_kernel(const float* __restrict__ colours,
                               float* __restrict__ out,
                               int N) {
    int t = blockIdx.x * blockDim.x + threadIdx.x;
    if (t >= NPIX / 2) return;

    ulonglong2 vv = reinterpret_cast<const ulonglong2*>(g_zidx)[t];

    float2 r, g, b;
    {
        unsigned long long v = vv.x;
        float rr = 0.f, gg = 0.f, bb = 0.f;
        if (v != SENTINEL) {
            int idx = (int)(unsigned int)(v & 0xFFFFFFFFULL);
            if (idx < N) {
                const float* cp = colours + (size_t)idx * 12;
                rr = fast_sigmoid(cp[0]);
                gg = fast_sigmoid(cp[1]);
                bb = fast_sigmoid(cp[2]);
            }
        }
        r.x = rr; g.x = gg; b.x = bb;
    }
    {
        unsigned long long v = vv.y;
        float rr = 0.f, gg = 0.f, bb = 0.f;
        if (v != SENTINEL) {
            int idx = (int)(unsigned int)(v & 0xFFFFFFFFULL);
            if (idx < N) {
                const float* cp = colours + (size_t)idx * 12;
                rr = fast_sigmoid(cp[0]);
                gg = fast_sigmoid(cp[1]);
                bb = fast_sigmoid(cp[2]);
            }
        }
        r.y = rr; g.y = gg; b.y = bb;
    }

    reinterpret_cast<float2*>(out)[t]                = r;
    reinterpret_cast<float2*>(out + NPIX)[t]         = g;
    reinterpret_cast<float2*>(out + 2 * NPIX)[t]     = b;
}

extern "C" void kernel_launch(void* const* d_in, const int* in_sizes, int n_in,
                              void* d_out, int out_size) {
    const float* means   = (const float*)d_in[0];  // [N,3]
    const float* colours = (const float*)d_in[1];  // [N,12]
    const float* Kmat    = (const float*)d_in[2];  // [3,3]
    const float* E       = (const float*)d_in[3];  // [4,4]
    float* out = (float*)d_out;                    // [3,H,W]

    int N = in_sizes[0] / 3;
    int N4 = N / 4;  // N = 1,351,680 divisible by 4

    void* zidx_ptr = nullptr;
    cudaGetSymbolAddress(&zidx_ptr, g_zidx);
    cudaMemsetAsync(zidx_ptr, 0xFF, (size_t)NPIX * sizeof(unsigned long long));

    const int TPB = 256;
    splat4_kernel<<<(N4 + TPB - 1) / TPB, TPB>>>(
        (const float4*)means, Kmat, E, N4);
    render2_kernel<<<((NPIX / 2) + TPB - 1) / TPB, TPB>>>(colours, out, N);
}